// round 12
// baseline (speedup 1.0000x reference)
#include <cuda_runtime.h>
#include <cstdint>

#define NTOK 262144
#define DF 128
#define CC 64
#define TILES 2048
#define GRID 152
#define NTHR 1024

// ---- static device scratch (per-CTA partials) ----
__device__ float g_Fpart[GRID * CC * DF];
__device__ int   g_cntpart[GRID * CC];
__device__ float g_f2part[GRID];
__device__ float g_s2part[CC];
__device__ float g_nc2[CC];

// ---- shared memory byte offsets ----
#define SM_ATF   0        // float[128*136] column-permuted tf32 tile (69632)
#define SM_FSUM  69632    // float[64*136]  class sums, permuted cols (34816)
#define SM_STAGE 104448   // float[128*66]  staging; ctf alias at init (33792)
#define SM_KRED  138240   // float[16][4][128] k-split reduce buf (32768)
#define SM_F2    171008   // float[128]
#define SM_C2    171520   // float[64]
#define SM_LBL   171776   // int[128]
#define SM_CNT   172288   // int[64]
#define SM_CNTT  172544   // int[64]
#define SM_LIST  172800   // u8[64*128]
#define SM_TOTAL 180992

__device__ __forceinline__ float tf32r(float x) {
    unsigned u;
    asm("cvt.rna.tf32.f32 %0, %1;" : "=r"(u) : "f"(x));
    return __uint_as_float(u);
}
__device__ __forceinline__ void mma_tf32(float* d, float a0, float a1,
                                         float a2, float a3,
                                         unsigned b0, unsigned b1) {
    asm volatile(
        "mma.sync.aligned.m16n8k8.row.col.f32.tf32.tf32.f32 "
        "{%0,%1,%2,%3}, {%4,%5,%6,%7}, {%8,%9}, {%0,%1,%2,%3};"
        : "+f"(d[0]), "+f"(d[1]), "+f"(d[2]), "+f"(d[3])
        : "r"(__float_as_uint(a0)), "r"(__float_as_uint(a1)),
          "r"(__float_as_uint(a2)), "r"(__float_as_uint(a3)),
          "r"(b0), "r"(b1));
}

// ============================================================
__global__ void __launch_bounds__(NTHR, 1)
k_main(const float* __restrict__ feature, const int* __restrict__ label,
       const float* __restrict__ centers, float* __restrict__ out)
{
    extern __shared__ __align__(16) char sm[];
    float*         atf     = (float*)(sm + SM_ATF);
    float*         F_sm    = (float*)(sm + SM_FSUM);
    float*         stage   = (float*)(sm + SM_STAGE);
    float*         ctf     = (float*)(sm + SM_STAGE);   // init-time alias
    float*         kred    = (float*)(sm + SM_KRED);
    float*         f2_sm   = (float*)(sm + SM_F2);
    float*         c2_sm   = (float*)(sm + SM_C2);
    int*           lbl_sm  = (int*)(sm + SM_LBL);
    int*           cnt_sm  = (int*)(sm + SM_CNT);
    int*           cntt_sm = (int*)(sm + SM_CNTT);
    unsigned char* list_sm = (unsigned char*)(sm + SM_LIST);

    const int tid = threadIdx.x, bid = blockIdx.x;
    const int w = tid >> 5, l = tid & 31;
    const int lq = l >> 2, lr = l & 3;
    const int wk = w >> 4;              // k-half (0,1)
    const int wm = (w >> 2) & 3;        // m-strip of 32 rows
    const int wn = w & 3;               // 16-class group

    // ---- one-time init: ctf (stage alias), c2, F_sm, cntt ----
    for (int i = tid; i < CC * 136; i += NTHR) F_sm[i] = 0.f;
    for (int i = tid; i < CC * DF; i += NTHR)
        ctf[(i >> 7) * 132 + (i & 127)] = tf32r(centers[i]);
    if (tid < CC) {
        float s = 0.f;
        for (int k = 0; k < DF; k++) { float c = centers[tid * DF + k]; s += c * c; }
        c2_sm[tid] = s;
        cntt_sm[tid] = 0;
    }
    __syncthreads();

    // ---- persistent B fragments for this warp's k-half: 32 regs ----
    unsigned bfr[8][2][2];
    #pragma unroll
    for (int kc = 0; kc < 8; kc++)
        #pragma unroll
        for (int bg = 0; bg < 2; bg++) {
            const float* cp = &ctf[(wn * 16 + bg * 8 + lq) * 132 + (wk * 8 + kc) * 8 + lr];
            bfr[kc][bg][0] = __float_as_uint(cp[0]);
            bfr[kc][bg][1] = __float_as_uint(cp[4]);
        }
    __syncthreads();                     // ctf consumed; stage free

    double f2acc = 0.0;

    for (int tile = bid; tile < TILES; tile += GRID) {
        __syncthreads();                 // S1: atf/stage/kred reusable
        const int base = tile * 128;

        if (tid < 128)      lbl_sm[tid] = label[base + tid] & (CC - 1);
        else if (tid < 192) cnt_sm[tid - 128] = 0;

        // ---- load + exact f2 + tf32 + column-permute (4 shfl) + STS ----
        #pragma unroll
        for (int it = 0; it < 4; it++) {
            const int row = it * 32 + w;      // warp covers one full row
            float4 f4 = *(const float4*)&feature[(size_t)(base + row) * DF + l * 4];
            float s = f4.x * f4.x + f4.y * f4.y + f4.z * f4.z + f4.w * f4.w;
            #pragma unroll
            for (int o = 16; o; o >>= 1) s += __shfl_xor_sync(0xffffffffu, s, o);
            if (l == 0) f2_sm[row] = s;
            f4.x = tf32r(f4.x); f4.y = tf32r(f4.y);
            f4.z = tf32r(f4.z); f4.w = tf32r(f4.w);
            const float sx = __shfl_xor_sync(0xffffffffu, f4.x, 1);
            const float sy = __shfl_xor_sync(0xffffffffu, f4.y, 1);
            const float sz = __shfl_xor_sync(0xffffffffu, f4.z, 1);
            const float sw = __shfl_xor_sync(0xffffffffu, f4.w, 1);
            const float4 o4 = (l & 1) ? make_float4(sz, f4.z, sw, f4.w)
                                      : make_float4(f4.x, sx, f4.y, sy);
            *(float4*)&atf[row * 136 + l * 4] = o4;
        }
        __syncthreads();                 // S2: tile + labels visible

        if (tid < 128) {
            int c = lbl_sm[tid];
            int pos = atomicAdd(&cnt_sm[c], 1);
            list_sm[c * 128 + pos] = (unsigned char)tid;
        }

        // ---- GEMM: half-K per warp, LDS.64 A-frags ----
        float acc[2][2][4];
        #pragma unroll
        for (int mi = 0; mi < 2; mi++)
            #pragma unroll
            for (int bg = 0; bg < 2; bg++)
                #pragma unroll
                for (int e = 0; e < 4; e++) acc[mi][bg][e] = 0.f;

        #pragma unroll
        for (int kc = 0; kc < 8; kc++) {
            #pragma unroll
            for (int mi = 0; mi < 2; mi++) {
                const float* ap = &atf[(wm * 32 + mi * 16 + lq) * 136
                                       + (wk * 8 + kc) * 8 + 2 * lr];
                const float2 A0 = *(const float2*)ap;             // (a0, a2)
                const float2 A1 = *(const float2*)(ap + 8 * 136); // (a1, a3)
                mma_tf32(acc[mi][0], A0.x, A1.x, A0.y, A1.y,
                         bfr[kc][0][0], bfr[kc][0][1]);
                mma_tf32(acc[mi][1], A0.x, A1.x, A0.y, A1.y,
                         bfr[kc][1][0], bfr[kc][1][1]);
            }
        }

        // ---- k1 warps publish partial accs ----
        if (wk == 1) {
            float* kr = kred + (w - 16) * 512;
            #pragma unroll
            for (int mi = 0; mi < 2; mi++)
                #pragma unroll
                for (int bg = 0; bg < 2; bg++)
                    *(float4*)&kr[(mi * 2 + bg) * 128 + l * 4] =
                        make_float4(acc[mi][bg][0], acc[mi][bg][1],
                                    acc[mi][bg][2], acc[mi][bg][3]);
        }
        __syncthreads();                 // S3: kred ready, lists complete

        if (wk == 0) {
            // ---- k-reduce + epilogue -> stage (stride 66) ----
            const float* kr = kred + w * 512;
            #pragma unroll
            for (int mi = 0; mi < 2; mi++) {
                const int R = wm * 32 + mi * 16;
                const float ft0 = f2_sm[R + lq], ft1 = f2_sm[R + lq + 8];
                #pragma unroll
                for (int bg = 0; bg < 2; bg++) {
                    const float4 v = *(const float4*)&kr[(mi * 2 + bg) * 128 + l * 4];
                    const float d0 = acc[mi][bg][0] + v.x;
                    const float d1 = acc[mi][bg][1] + v.y;
                    const float d2 = acc[mi][bg][2] + v.z;
                    const float d3 = acc[mi][bg][3] + v.w;
                    const int n0 = wn * 16 + bg * 8 + 2 * lr;
                    const float cA = c2_sm[n0], cB = c2_sm[n0 + 1];
                    float2 v0, v1;
                    v0.x = fmaf(-2.f, d0, ft0 + cA);
                    v0.y = fmaf(-2.f, d1, ft0 + cB);
                    v1.x = fmaf(-2.f, d2, ft1 + cA);
                    v1.y = fmaf(-2.f, d3, ft1 + cB);
                    *(float2*)&stage[(R + lq) * 66 + n0] = v0;
                    *(float2*)&stage[(R + lq + 8) * 66 + n0] = v1;
                }
            }
        } else {
            // ---- phase 3: k1 warp owns 4 classes (permuted cols) ----
            const int wp = w - 16;
            #pragma unroll
            for (int cc = 0; cc < 4; cc++) {
                const int c = wp * 4 + cc;
                const int n = cnt_sm[c];
                if (n) {
                    const unsigned char* lst = list_sm + c * 128;
                    float4 a = make_float4(0.f, 0.f, 0.f, 0.f);
                    for (int t = 0; t < n; t++) {
                        const int r = lst[t];
                        const float4 v = *(const float4*)&atf[r * 136 + l * 4];
                        a.x += v.x; a.y += v.y; a.z += v.z; a.w += v.w;
                    }
                    float4* Fp = (float4*)&F_sm[c * 136 + l * 4];
                    float4 f = *Fp;
                    f.x += a.x; f.y += a.y; f.z += a.z; f.w += a.w;
                    *Fp = f;
                }
            }
        }
        if (tid < CC)  cntt_sm[tid] += cnt_sm[tid];
        if (tid < 128) f2acc += (double)f2_sm[tid];
        __syncthreads();                 // S4: stage ready

        // ---- flat aligned store: out + 8193 + tile*8192 ----
        float* gdst = out + 1 + CC * DF + (size_t)tile * 8192;
        if (tid < 4) {
            if (tid < 3) gdst[tid] = stage[tid];
            else         gdst[8191] = stage[127 * 66 + 63];
        }
        for (int qq = tid; qq < 2047; qq += NTHR) {
            const int j0 = 3 + 4 * qq;
            float4 v;
            v.x = stage[((j0 + 0) >> 6) * 66 + ((j0 + 0) & 63)];
            v.y = stage[((j0 + 1) >> 6) * 66 + ((j0 + 1) & 63)];
            v.z = stage[((j0 + 2) >> 6) * 66 + ((j0 + 2) & 63)];
            v.w = stage[((j0 + 3) >> 6) * 66 + ((j0 + 3) & 63)];
            *(float4*)(gdst + j0) = v;
        }
    }

    // ---- flush per-CTA partials (un-permute columns) ----
    __syncthreads();
    for (int i = tid; i < CC * DF; i += NTHR) {
        const int c = i >> 7, pos = i & 127;
        const int u = pos & 7;
        const int col = (pos >> 3) * 8 + (u >> 1) + 4 * (u & 1);
        g_Fpart[bid * CC * DF + c * 128 + col] = F_sm[c * 136 + pos];
    }
    if (tid < CC) g_cntpart[bid * CC + tid] = cntt_sm[tid];
    {
        double* dred = (double*)(sm + SM_STAGE);
        dred[tid] = (tid < 128) ? f2acc : 0.0;
        __syncthreads();
        if (tid == 0) {
            double s0 = 0, s1 = 0, s2 = 0, s3 = 0;
            for (int i = 0; i < 128; i += 4) {
                s0 += dred[i]; s1 += dred[i + 1]; s2 += dred[i + 2]; s3 += dred[i + 3];
            }
            g_f2part[bid] = (float)((s0 + s1) + (s2 + s3));
        }
    }
}

// ============================================================
// finalize 1: one block per class (64 x 128 threads)
// ============================================================
__global__ void __launch_bounds__(128)
k_final1(const float* __restrict__ centers, float* __restrict__ out)
{
    __shared__ float red[128];
    __shared__ int   ired[128];
    __shared__ int   ncls;
    const int c = blockIdx.x, t = threadIdx.x;

    int s = (t < GRID) ? g_cntpart[t * CC + c] : 0;
    if (t + 128 < GRID) s += g_cntpart[(t + 128) * CC + c];
    ired[t] = s;
    __syncthreads();
    for (int off = 64; off; off >>= 1) {
        if (t < off) ired[t] += ired[t + off];
        __syncthreads();
    }
    if (t == 0) ncls = ired[0];
    __syncthreads();
    const int n = ncls;

    const int i = c * DF + t;
    float F0 = 0, F1 = 0, F2 = 0, F3 = 0, F4 = 0, F5 = 0, F6 = 0, F7 = 0;
    #pragma unroll 4
    for (int b = 0; b < GRID; b += 8) {
        F0 += g_Fpart[(b + 0) * CC * DF + i];
        F1 += g_Fpart[(b + 1) * CC * DF + i];
        F2 += g_Fpart[(b + 2) * CC * DF + i];
        F3 += g_Fpart[(b + 3) * CC * DF + i];
        F4 += g_Fpart[(b + 4) * CC * DF + i];
        F5 += g_Fpart[(b + 5) * CC * DF + i];
        F6 += g_Fpart[(b + 6) * CC * DF + i];
        F7 += g_Fpart[(b + 7) * CC * DF + i];
    }
    const float F = ((F0 + F1) + (F2 + F3)) + ((F4 + F5) + (F6 + F7));
    const float cen = centers[i];
    out[1 + i] = (n > 0) ? (cen - F / (float)n) : 0.f;

    red[t] = F * cen;
    __syncthreads();
    for (int off = 64; off; off >>= 1) {
        if (t < off) red[t] += red[t + off];
        __syncthreads();
    }
    if (t == 0) g_s2part[c] = red[0];
    __syncthreads();
    red[t] = cen * cen;
    __syncthreads();
    for (int off = 64; off; off >>= 1) {
        if (t < off) red[t] += red[t + off];
        __syncthreads();
    }
    if (t == 0) g_nc2[c] = (float)n * red[0];
}

// ============================================================
// finalize 2: micro kernel for the loss scalar
// ============================================================
__global__ void __launch_bounds__(128)
k_final2(float* __restrict__ out)
{
    __shared__ float r1[128], r2[128], r3[128];
    const int t = threadIdx.x;
    float a = (t < GRID) ? g_f2part[t] : 0.f;
    if (t + 128 < GRID) a += g_f2part[t + 128];
    r1[t] = a;
    r2[t] = (t < CC) ? g_s2part[t] : 0.f;
    r3[t] = (t < CC) ? g_nc2[t] : 0.f;
    __syncthreads();
    for (int off = 64; off; off >>= 1) {
        if (t < off) { r1[t] += r1[t + off]; r2[t] += r2[t + off]; r3[t] += r3[t + off]; }
        __syncthreads();
    }
    if (t == 0)
        out[0] = (float)(((double)r1[0] - 2.0 * (double)r2[0] + (double)r3[0])
                         / ((double)NTOK * (double)DF));
}

// ============================================================
extern "C" void kernel_launch(void* const* d_in, const int* in_sizes, int n_in,
                              void* d_out, int out_size)
{
    const float* feature = (const float*)d_in[0];
    const int*   label   = (const int*)d_in[1];
    const float* centers = (const float*)d_in[2];
    float*       out     = (float*)d_out;

    cudaFuncSetAttribute(k_main, cudaFuncAttributeMaxDynamicSharedMemorySize, SM_TOTAL);
    k_main<<<GRID, NTHR, SM_TOTAL>>>(feature, label, centers, out);
    k_final1<<<CC, 128>>>(centers, out);
    k_final2<<<1, 128>>>(out);
}

// round 13
// speedup vs baseline: 1.0343x; 1.0343x over previous
#include <cuda_runtime.h>
#include <cstdint>

#define NTOK 262144
#define DF 128
#define CC 64
#define TILES 2048
#define GRID 152
#define NTHR 512

// ---- static device scratch (per-CTA partials) ----
__device__ float g_Fpart[GRID * CC * DF];
__device__ int   g_cntpart[GRID * CC];
__device__ float g_f2part[GRID];
__device__ float g_s2part[CC];
__device__ float g_nc2[CC];

// ---- shared memory byte offsets ----
#define SM_ATF   0          // float[128*132] tf32-rounded feature tile
#define SM_CTF   67584      // float[64*132]  tf32-rounded centers
#define SM_FSUM  101376     // float[64*132]  per-CTA class sums
#define SM_DRED  135168     // double[128] final f2 reduce (ctf alias until end)
#define SM_F2    169472     // float[128]
#define SM_C2    169984     // float[64]
#define SM_LBL   170240     // int[128]
#define SM_CNT   170752     // int[64]
#define SM_CNTT  171008     // int[64]
#define SM_LIST  171264     // u8[64*128]
#define SM_TOTAL 179456

__device__ __forceinline__ float tf32r(float x) {
    unsigned u;
    asm("cvt.rna.tf32.f32 %0, %1;" : "=r"(u) : "f"(x));
    return __uint_as_float(u);
}
__device__ __forceinline__ void mma_tf32(float* d, unsigned a0, unsigned a1,
                                         unsigned a2, unsigned a3,
                                         unsigned b0, unsigned b1) {
    asm volatile(
        "mma.sync.aligned.m16n8k8.row.col.f32.tf32.tf32.f32 "
        "{%0,%1,%2,%3}, {%4,%5,%6,%7}, {%8,%9}, {%0,%1,%2,%3};"
        : "+f"(d[0]), "+f"(d[1]), "+f"(d[2]), "+f"(d[3])
        : "r"(a0), "r"(a1), "r"(a2), "r"(a3), "r"(b0), "r"(b1));
}

// ============================================================
__global__ void __launch_bounds__(NTHR, 1)
k_main(const float* __restrict__ feature, const int* __restrict__ label,
       const float* __restrict__ centers, float* __restrict__ out)
{
    extern __shared__ __align__(16) char sm[];
    float*         atf     = (float*)(sm + SM_ATF);
    float*         ctf     = (float*)(sm + SM_CTF);
    float*         F_sm    = (float*)(sm + SM_FSUM);
    float*         f2_sm   = (float*)(sm + SM_F2);
    float*         c2_sm   = (float*)(sm + SM_C2);
    int*           lbl_sm  = (int*)(sm + SM_LBL);
    int*           cnt_sm  = (int*)(sm + SM_CNT);
    int*           cntt_sm = (int*)(sm + SM_CNTT);
    unsigned char* list_sm = (unsigned char*)(sm + SM_LIST);

    const int tid = threadIdx.x, bid = blockIdx.x;
    const int w = tid >> 5, l = tid & 31;
    const int lq = l >> 2, lr = l & 3;
    const int mbase = (w >> 2) * 32;            // 4 m-groups of 32 tokens
    const int nbase = (w & 3) * 16;             // 4 n-groups of 16 classes

    // ---- one-time init ----
    for (int i = tid; i < CC * 132; i += NTHR) F_sm[i] = 0.f;
    for (int i = tid; i < CC * DF; i += NTHR) {
        int n = i >> 7, k = i & 127;
        ctf[n * 132 + k] = tf32r(centers[i]);
    }
    if (tid < CC) {
        float s = 0.f;
        for (int k = 0; k < DF; k++) { float c = centers[tid * DF + k]; s += c * c; }
        c2_sm[tid] = s;
        cntt_sm[tid] = 0;
    }
    __syncthreads();

    // ---- persistent B fragments: classes nbase..nbase+15, all K ----
    unsigned bfr[16][2][2];
    #pragma unroll
    for (int kc = 0; kc < 16; kc++)
        #pragma unroll
        for (int j = 0; j < 2; j++) {
            const float* cp = &ctf[(nbase + j * 8 + lq) * 132 + kc * 8 + lr];
            bfr[kc][j][0] = __float_as_uint(cp[0]);
            bfr[kc][j][1] = __float_as_uint(cp[4]);
        }

    double f2acc = 0.0;

    for (int tile = bid; tile < TILES; tile += GRID) {
        __syncthreads();                         // S1: atf reuse safe (prev phase3 done)
        const int base = tile * 128;

        if (tid < 128)      lbl_sm[tid] = label[base + tid] & (CC - 1);
        else if (tid < 192) cnt_sm[tid - 128] = 0;

        // ---- load, exact f2, tf32-round, store tile ----
        #pragma unroll
        for (int it = 0; it < 8; it++) {
            const int v = it * NTHR + tid;
            const int tok = v >> 5, i4 = v & 31;    // warp = one token row
            float4 f4 = *(const float4*)&feature[(size_t)(base + tok) * DF + i4 * 4];
            float s = f4.x * f4.x + f4.y * f4.y + f4.z * f4.z + f4.w * f4.w;
            #pragma unroll
            for (int o = 16; o; o >>= 1) s += __shfl_xor_sync(0xffffffffu, s, o);
            if (l == 0) f2_sm[tok] = s;
            f4.x = tf32r(f4.x); f4.y = tf32r(f4.y);
            f4.z = tf32r(f4.z); f4.w = tf32r(f4.w);
            *(float4*)&atf[tok * 132 + i4 * 4] = f4;
        }
        __syncthreads();                         // S2: tile + labels visible

        // ---- per-tile class row lists ----
        if (tid < 128) {
            int c = lbl_sm[tid];
            int pos = atomicAdd(&cnt_sm[c], 1);
            list_sm[c * 128 + pos] = (unsigned char)tid;
        }

        // ---- GEMM: 32 tokens x 16 classes per warp, TF32 HMMA ----
        float acc[2][2][4];
        #pragma unroll
        for (int mi = 0; mi < 2; mi++)
            #pragma unroll
            for (int j = 0; j < 2; j++)
                #pragma unroll
                for (int e = 0; e < 4; e++) acc[mi][j][e] = 0.f;

        #pragma unroll
        for (int kc = 0; kc < 16; kc++) {
            #pragma unroll
            for (int mi = 0; mi < 2; mi++) {
                const float* ap = &atf[(mbase + mi * 16 + lq) * 132 + kc * 8 + lr];
                unsigned a0 = __float_as_uint(ap[0]);
                unsigned a2 = __float_as_uint(ap[4]);
                unsigned a1 = __float_as_uint(ap[8 * 132]);
                unsigned a3 = __float_as_uint(ap[8 * 132 + 4]);
                mma_tf32(acc[mi][0], a0, a1, a2, a3, bfr[kc][0][0], bfr[kc][0][1]);
                mma_tf32(acc[mi][1], a0, a1, a2, a3, bfr[kc][1][0], bfr[kc][1][1]);
            }
        }

        // ---- epilogue: dist = f2 + c2 - 2*dot, DIRECT scalar STG ----
        {
            float* gdst = out + 1 + CC * DF + (size_t)tile * 8192;
            #pragma unroll
            for (int mi = 0; mi < 2; mi++) {
                const int r0 = mbase + mi * 16 + lq;
                const float ft0 = f2_sm[r0], ft1 = f2_sm[r0 + 8];
                #pragma unroll
                for (int j = 0; j < 2; j++) {
                    const int n0 = nbase + j * 8 + lr * 2;
                    const float cA = c2_sm[n0], cB = c2_sm[n0 + 1];
                    gdst[r0 * CC + n0]           = fmaf(-2.f, acc[mi][j][0], ft0 + cA);
                    gdst[r0 * CC + n0 + 1]       = fmaf(-2.f, acc[mi][j][1], ft0 + cB);
                    gdst[(r0 + 8) * CC + n0]     = fmaf(-2.f, acc[mi][j][2], ft1 + cA);
                    gdst[(r0 + 8) * CC + n0 + 1] = fmaf(-2.f, acc[mi][j][3], ft1 + cB);
                }
            }
        }
        __syncthreads();                         // S3: lists complete

        // ---- phase 3: warp owns 4 classes; whole class row in registers ----
        {
            #pragma unroll
            for (int cc = 0; cc < 4; cc++) {
                const int c = w * 4 + cc;
                const int n = cnt_sm[c];
                if (n) {
                    const unsigned char* lst = list_sm + c * 128;
                    float4 a = make_float4(0.f, 0.f, 0.f, 0.f);
                    for (int i = 0; i < n; i++) {
                        const int r = lst[i];                    // broadcast LDS
                        const float4 v = *(const float4*)&atf[r * 132 + l * 4];
                        a.x += v.x; a.y += v.y; a.z += v.z; a.w += v.w;
                    }
                    float4* Fp = (float4*)&F_sm[c * 132 + l * 4];
                    float4 f = *Fp;
                    f.x += a.x; f.y += a.y; f.z += a.z; f.w += a.w;
                    *Fp = f;
                }
            }
        }
        if (tid < CC)  cntt_sm[tid] += cnt_sm[tid];
        if (tid < 128) f2acc += (double)f2_sm[tid];
    }

    // ---- flush per-CTA partials (deterministic slots) ----
    __syncthreads();
    for (int i = tid; i < CC * DF; i += NTHR)
        g_Fpart[bid * CC * DF + i] = F_sm[(i >> 7) * 132 + (i & 127)];
    if (tid < CC) g_cntpart[bid * CC + tid] = cntt_sm[tid];
    {
        double* dred = (double*)(sm + SM_DRED);
        dred[tid] = (tid < 128) ? f2acc : 0.0;
        __syncthreads();
        if (tid == 0) {
            double s0 = 0, s1 = 0, s2 = 0, s3 = 0;
            for (int i = 0; i < 128; i += 4) {
                s0 += dred[i]; s1 += dred[i + 1]; s2 += dred[i + 2]; s3 += dred[i + 3];
            }
            g_f2part[bid] = (float)((s0 + s1) + (s2 + s3));
        }
    }
}

// ============================================================
// finalize 1: one block per class (64 x 128 threads)
// ============================================================
__global__ void __launch_bounds__(128)
k_final1(const float* __restrict__ centers, float* __restrict__ out)
{
    __shared__ float red[128];
    __shared__ int   ired[128];
    __shared__ int   ncls;
    const int c = blockIdx.x, t = threadIdx.x;

    int s = (t < GRID) ? g_cntpart[t * CC + c] : 0;
    if (t + 128 < GRID) s += g_cntpart[(t + 128) * CC + c];
    ired[t] = s;
    __syncthreads();
    for (int off = 64; off; off >>= 1) {
        if (t < off) ired[t] += ired[t + off];
        __syncthreads();
    }
    if (t == 0) ncls = ired[0];
    __syncthreads();
    const int n = ncls;

    const int i = c * DF + t;
    float F0 = 0, F1 = 0, F2 = 0, F3 = 0, F4 = 0, F5 = 0, F6 = 0, F7 = 0;
    #pragma unroll 4
    for (int b = 0; b < GRID; b += 8) {
        F0 += g_Fpart[(b + 0) * CC * DF + i];
        F1 += g_Fpart[(b + 1) * CC * DF + i];
        F2 += g_Fpart[(b + 2) * CC * DF + i];
        F3 += g_Fpart[(b + 3) * CC * DF + i];
        F4 += g_Fpart[(b + 4) * CC * DF + i];
        F5 += g_Fpart[(b + 5) * CC * DF + i];
        F6 += g_Fpart[(b + 6) * CC * DF + i];
        F7 += g_Fpart[(b + 7) * CC * DF + i];
    }
    const float F = ((F0 + F1) + (F2 + F3)) + ((F4 + F5) + (F6 + F7));
    const float cen = centers[i];
    out[1 + i] = (n > 0) ? (cen - F / (float)n) : 0.f;

    red[t] = F * cen;
    __syncthreads();
    for (int off = 64; off; off >>= 1) {
        if (t < off) red[t] += red[t + off];
        __syncthreads();
    }
    if (t == 0) g_s2part[c] = red[0];
    __syncthreads();
    red[t] = cen * cen;
    __syncthreads();
    for (int off = 64; off; off >>= 1) {
        if (t < off) red[t] += red[t + off];
        __syncthreads();
    }
    if (t == 0) g_nc2[c] = (float)n * red[0];
}

// ============================================================
// finalize 2: micro kernel for the loss scalar
// ============================================================
__global__ void __launch_bounds__(128)
k_final2(float* __restrict__ out)
{
    __shared__ float r1[128], r2[128], r3[128];
    const int t = threadIdx.x;
    float a = (t < GRID) ? g_f2part[t] : 0.f;
    if (t + 128 < GRID) a += g_f2part[t + 128];
    r1[t] = a;
    r2[t] = (t < CC) ? g_s2part[t] : 0.f;
    r3[t] = (t < CC) ? g_nc2[t] : 0.f;
    __syncthreads();
    for (int off = 64; off; off >>= 1) {
        if (t < off) { r1[t] += r1[t + off]; r2[t] += r2[t + off]; r3[t] += r3[t + off]; }
        __syncthreads();
    }
    if (t == 0)
        out[0] = (float)(((double)r1[0] - 2.0 * (double)r2[0] + (double)r3[0])
                         / ((double)NTOK * (double)DF));
}

// ============================================================
extern "C" void kernel_launch(void* const* d_in, const int* in_sizes, int n_in,
                              void* d_out, int out_size)
{
    const float* feature = (const float*)d_in[0];
    const int*   label   = (const int*)d_in[1];
    const float* centers = (const float*)d_in[2];
    float*       out     = (float*)d_out;

    cudaFuncSetAttribute(k_main, cudaFuncAttributeMaxDynamicSharedMemorySize, SM_TOTAL);
    k_main<<<GRID, NTHR, SM_TOTAL>>>(feature, label, centers, out);
    k_final1<<<CC, 128>>>(centers, out);
    k_final2<<<1, 128>>>(out);
}